// round 9
// baseline (speedup 1.0000x reference)
#include <cuda_runtime.h>
#include <cuda_bf16.h>

// Problem constants
#define BB 2
#define LL 384
#define EE 512
#define HH 8
#define HD 64
#define BH 16            // BB*HH
#define MROWS 768        // BB*LL
#define CATOMS 16        // HD/4
#define JS 8             // j-splits for parallelism
#define JCHUNK 48        // LL/JS
#define EPSQ 1e-6f

// Scratch (no allocations allowed -> device globals)
__device__ float g_q[BH * LL * HD];
__device__ float g_k[BH * LL * HD];
__device__ float g_v[BH * LL * HD];
__device__ float g_part[JS * BH * LL * HD];
__device__ float g_ctx[MROWS * EE];

// ---------------------------------------------------------------------------
// QKV projection: C[m,f] = sum_e x[m,e] * W[f,e], scattered into
// (bh, l, d) head-major layout. grid = (8, 12, 3), block = 256.
// 64x64 output tile, 16-wide K tiles, 4x4 micro-tile per thread.
// ---------------------------------------------------------------------------
__global__ __launch_bounds__(256) void qkv_gemm_kernel(
    const float* __restrict__ x,
    const float* __restrict__ Wq,
    const float* __restrict__ Wk,
    const float* __restrict__ Wv)
{
    __shared__ __align__(16) float As[16][64];
    __shared__ __align__(16) float Bs[16][64];

    const int which = blockIdx.z;
    const float* W = (which == 0) ? Wq : (which == 1 ? Wk : Wv);
    float* out = (which == 0) ? g_q : (which == 1 ? g_k : g_v);

    const int m0 = blockIdx.y * 64;
    const int n0 = blockIdx.x * 64;
    const int tid = threadIdx.x;
    const int tx = tid & 15;
    const int ty = tid >> 4;
    const int lrow = tid >> 2;          // 0..63
    const int lk4 = (tid & 3) << 2;     // 0,4,8,12

    const float* Ap = x + (m0 + lrow) * EE;
    const float* Bp = W + (n0 + lrow) * EE;

    float acc[4][4];
#pragma unroll
    for (int i = 0; i < 4; i++)
#pragma unroll
        for (int j = 0; j < 4; j++) acc[i][j] = 0.0f;

    for (int k0 = 0; k0 < EE; k0 += 16) {
        float4 av = *(const float4*)(Ap + k0 + lk4);
        float4 bv = *(const float4*)(Bp + k0 + lk4);
        As[lk4 + 0][lrow] = av.x; As[lk4 + 1][lrow] = av.y;
        As[lk4 + 2][lrow] = av.z; As[lk4 + 3][lrow] = av.w;
        Bs[lk4 + 0][lrow] = bv.x; Bs[lk4 + 1][lrow] = bv.y;
        Bs[lk4 + 2][lrow] = bv.z; Bs[lk4 + 3][lrow] = bv.w;
        __syncthreads();
#pragma unroll
        for (int kk = 0; kk < 16; kk++) {
            float4 a4 = *(const float4*)&As[kk][ty << 2];
            float4 b4 = *(const float4*)&Bs[kk][tx << 2];
            acc[0][0] += a4.x * b4.x; acc[0][1] += a4.x * b4.y;
            acc[0][2] += a4.x * b4.z; acc[0][3] += a4.x * b4.w;
            acc[1][0] += a4.y * b4.x; acc[1][1] += a4.y * b4.y;
            acc[1][2] += a4.y * b4.z; acc[1][3] += a4.y * b4.w;
            acc[2][0] += a4.z * b4.x; acc[2][1] += a4.z * b4.y;
            acc[2][2] += a4.z * b4.z; acc[2][3] += a4.z * b4.w;
            acc[3][0] += a4.w * b4.x; acc[3][1] += a4.w * b4.y;
            acc[3][2] += a4.w * b4.z; acc[3][3] += a4.w * b4.w;
        }
        __syncthreads();
    }

    // Scatter to head-major (bh, l, d). Tile is fully inside one b (384 % 64
    // == 0) and one head (n0 multiple of 64).
    const int b = m0 / LL;
    const int h = n0 >> 6;
    const int lbase = m0 - b * LL;
#pragma unroll
    for (int i = 0; i < 4; i++) {
        int l = lbase + (ty << 2) + i;
        float4 vst = make_float4(acc[i][0], acc[i][1], acc[i][2], acc[i][3]);
        *(float4*)(out + (((b << 3) + h) * LL + l) * HD + (tx << 2)) = vst;
    }
}

// ---------------------------------------------------------------------------
// Quaternion attention. grid = (6, 16, 8), block = 128.
// 2 threads per query row (8 atoms each), K/V chunk in smem,
// gate mean via one shfl_xor, fp32 FMA throughout.
// ---------------------------------------------------------------------------
__global__ __launch_bounds__(128) void attn_kernel(
    const float* __restrict__ dde_w,
    const float* __restrict__ dde_b)
{
    __shared__ float4 sk[JCHUNK * CATOMS];
    __shared__ float4 sv[JCHUNK * CATOMS];

    const int tid = threadIdx.x;
    const int rb = blockIdx.x;   // row block (64 rows)
    const int bh = blockIdx.y;
    const int js = blockIdx.z;
    const int j0 = js * JCHUNK;

    // Stage K/V chunk: 48 keys x 16 atoms (float4) each
    const float4* kg = (const float4*)(g_k + (bh * LL + j0) * HD);
    const float4* vg = (const float4*)(g_v + (bh * LL + j0) * HD);
    for (int t = tid; t < JCHUNK * CATOMS; t += 128) {
        sk[t] = kg[t];
        sv[t] = vg[t];
    }

    // Gate weights into registers (broadcast loads)
    float w[16], bvec[4];
#pragma unroll
    for (int p = 0; p < 16; p++) w[p] = __ldg(&dde_w[p]);
#pragma unroll
    for (int p = 0; p < 4; p++) bvec[p] = __ldg(&dde_b[p]);

    const int row = rb * 64 + (tid >> 1);
    const int half = tid & 1;

    // q atoms (this thread owns 8 of 16)
    float4 q[8];
    const float4* qg = (const float4*)(g_q + (bh * LL + row) * HD);
#pragma unroll
    for (int a = 0; a < 8; a++) q[a] = qg[half * 8 + a];

    float4 ctx[8];
#pragma unroll
    for (int a = 0; a < 8; a++) ctx[a] = make_float4(0.f, 0.f, 0.f, 0.f);

    __syncthreads();

    for (int jj = 0; jj < JCHUNK; jj++) {
        float4 s[8];
        float g0 = 0.f, g1 = 0.f, g2 = 0.f, g3 = 0.f;
        const float4* kbase = &sk[jj * CATOMS + half * 8];
#pragma unroll
        for (int a = 0; a < 8; a++) {
            float4 kk = kbase[a];
            float4 qa = q[a];
            // Hamilton(q, k); memory order (.x,.y,.z,.w) = (w,x,y,z)
            float hw = qa.x * kk.x - qa.y * kk.y - qa.z * kk.z - qa.w * kk.w;
            float hx = qa.x * kk.y + qa.y * kk.x + qa.z * kk.w - qa.w * kk.z;
            float hy = qa.x * kk.z - qa.y * kk.w + qa.z * kk.x + qa.w * kk.y;
            float hz = qa.x * kk.w + qa.y * kk.z - qa.z * kk.y + qa.w * kk.x;
            float d = hw * hw + hx * hx + hy * hy + hz * hz;
            float inv = __fdividef(1.0f, sqrtf(d) + EPSQ);
            float4 sa = make_float4(hw * inv, hx * inv, hy * inv, hz * inv);
            s[a] = sa;
            g0 += sa.x; g1 += sa.y; g2 += sa.z; g3 += sa.w;
        }
        // Sum across the row's two halves -> full 16-atom sum on both lanes
        g0 += __shfl_xor_sync(0xffffffffu, g0, 1);
        g1 += __shfl_xor_sync(0xffffffffu, g1, 1);
        g2 += __shfl_xor_sync(0xffffffffu, g2, 1);
        g3 += __shfl_xor_sync(0xffffffffu, g3, 1);
        const float inv16 = 1.0f / 16.0f;
        g0 *= inv16; g1 *= inv16; g2 *= inv16; g3 *= inv16;

        float gate[4];
#pragma unroll
        for (int p = 0; p < 4; p++) {
            float z = w[p * 4 + 0] * g0 + w[p * 4 + 1] * g1 +
                      w[p * 4 + 2] * g2 + w[p * 4 + 3] * g3 + bvec[p];
            gate[p] = __fdividef(1.0f, 1.0f + __expf(-z));
        }

        const float4* vbase = &sv[jj * CATOMS + half * 8];
#pragma unroll
        for (int a = 0; a < 8; a++) {
            float4 vv = vbase[a];
            float aw = s[a].x * gate[0];
            float ax = s[a].y * gate[1];
            float ay = s[a].z * gate[2];
            float az = s[a].w * gate[3];
            ctx[a].x += aw * vv.x - ax * vv.y - ay * vv.z - az * vv.w;
            ctx[a].y += aw * vv.y + ax * vv.x + ay * vv.w - az * vv.z;
            ctx[a].z += aw * vv.z - ax * vv.w + ay * vv.x + az * vv.y;
            ctx[a].w += aw * vv.w + ax * vv.z - ay * vv.y + az * vv.x;
        }
    }

    float4* pg = (float4*)(g_part + ((size_t)(js * BH + bh) * LL + row) * HD);
#pragma unroll
    for (int a = 0; a < 8; a++) pg[half * 8 + a] = ctx[a];
}

// ---------------------------------------------------------------------------
// Reduce JS partials + permute (bh,l,d) -> (m, e) GEMM layout.
// grid = 384, block = 256 (one float4 of g_ctx per thread).
// ---------------------------------------------------------------------------
__global__ __launch_bounds__(256) void reduce_kernel()
{
    int idx = blockIdx.x * 256 + threadIdx.x;     // over 98304 float4s
    int flat = idx << 2;
    int m = flat >> 9;            // /512
    int e = flat & 511;
    int b = m / LL;
    int l = m - b * LL;
    int h = e >> 6;
    int d = e & 63;
    float4 acc = make_float4(0.f, 0.f, 0.f, 0.f);
#pragma unroll
    for (int js = 0; js < JS; js++) {
        float4 p = *(const float4*)(g_part +
            ((size_t)(js * BH + (b << 3) + h) * LL + l) * HD + d);
        acc.x += p.x; acc.y += p.y; acc.z += p.z; acc.w += p.w;
    }
    *(float4*)(g_ctx + flat) = acc;
}

// ---------------------------------------------------------------------------
// Output projection: out[m,f] = sum_e ctx[m,e] * Wo[f,e].
// grid = (8, 12), block = 256. Same tiling as qkv_gemm.
// ---------------------------------------------------------------------------
__global__ __launch_bounds__(256) void out_gemm_kernel(
    const float* __restrict__ Wo, float* __restrict__ out)
{
    __shared__ __align__(16) float As[16][64];
    __shared__ __align__(16) float Bs[16][64];

    const int m0 = blockIdx.y * 64;
    const int n0 = blockIdx.x * 64;
    const int tid = threadIdx.x;
    const int tx = tid & 15;
    const int ty = tid >> 4;
    const int lrow = tid >> 2;
    const int lk4 = (tid & 3) << 2;

    const float* Ap = g_ctx + (m0 + lrow) * EE;
    const float* Bp = Wo + (n0 + lrow) * EE;

    float acc[4][4];
#pragma unroll
    for (int i = 0; i < 4; i++)
#pragma unroll
        for (int j = 0; j < 4; j++) acc[i][j] = 0.0f;

    for (int k0 = 0; k0 < EE; k0 += 16) {
        float4 av = *(const float4*)(Ap + k0 + lk4);
        float4 bv = *(const float4*)(Bp + k0 + lk4);
        As[lk4 + 0][lrow] = av.x; As[lk4 + 1][lrow] = av.y;
        As[lk4 + 2][lrow] = av.z; As[lk4 + 3][lrow] = av.w;
        Bs[lk4 + 0][lrow] = bv.x; Bs[lk4 + 1][lrow] = bv.y;
        Bs[lk4 + 2][lrow] = bv.z; Bs[lk4 + 3][lrow] = bv.w;
        __syncthreads();
#pragma unroll
        for (int kk = 0; kk < 16; kk++) {
            float4 a4 = *(const float4*)&As[kk][ty << 2];
            float4 b4 = *(const float4*)&Bs[kk][tx << 2];
            acc[0][0] += a4.x * b4.x; acc[0][1] += a4.x * b4.y;
            acc[0][2] += a4.x * b4.z; acc[0][3] += a4.x * b4.w;
            acc[1][0] += a4.y * b4.x; acc[1][1] += a4.y * b4.y;
            acc[1][2] += a4.y * b4.z; acc[1][3] += a4.y * b4.w;
            acc[2][0] += a4.z * b4.x; acc[2][1] += a4.z * b4.y;
            acc[2][2] += a4.z * b4.z; acc[2][3] += a4.z * b4.w;
            acc[3][0] += a4.w * b4.x; acc[3][1] += a4.w * b4.y;
            acc[3][2] += a4.w * b4.z; acc[3][3] += a4.w * b4.w;
        }
        __syncthreads();
    }

#pragma unroll
    for (int i = 0; i < 4; i++) {
        int m = m0 + (ty << 2) + i;
        float4 vst = make_float4(acc[i][0], acc[i][1], acc[i][2], acc[i][3]);
        *(float4*)(out + m * EE + n0 + (tx << 2)) = vst;
    }
}

// ---------------------------------------------------------------------------
extern "C" void kernel_launch(void* const* d_in, const int* in_sizes, int n_in,
                              void* d_out, int out_size)
{
    const float* x     = (const float*)d_in[0];
    const float* Wq    = (const float*)d_in[1];
    const float* Wk    = (const float*)d_in[2];
    const float* Wv    = (const float*)d_in[3];
    const float* Wo    = (const float*)d_in[4];
    const float* dde_w = (const float*)d_in[5];
    const float* dde_b = (const float*)d_in[6];
    float* out = (float*)d_out;

    qkv_gemm_kernel<<<dim3(8, 12, 3), 256>>>(x, Wq, Wk, Wv);
    attn_kernel<<<dim3(6, BH, JS), 128>>>(dde_w, dde_b);
    reduce_kernel<<<384, 256>>>();
    out_gemm_kernel<<<dim3(8, 12), 256>>>(Wo, out);
}

// round 10
// speedup vs baseline: 1.0029x; 1.0029x over previous
#include <cuda_runtime.h>
#include <cuda_bf16.h>

// Problem constants
#define BB 2
#define LL 384
#define EE 512
#define HH 8
#define HD 64
#define BH 16            // BB*HH
#define MROWS 768        // BB*LL
#define CATOMS 16        // HD/4
#define JS 8             // j-splits for parallelism
#define JCHUNK 48        // LL/JS
#define EPSQ 1e-6f

// Scratch (no allocations allowed -> device globals)
__device__ float g_q[BH * LL * HD];
__device__ float g_k[BH * LL * HD];
__device__ float g_v[BH * LL * HD];
__device__ float g_part[JS * BH * LL * HD];
__device__ float g_ctx[MROWS * EE];

// ---------------------------------------------------------------------------
// QKV projection: C[m,f] = sum_e x[m,e] * W[f,e], scattered into
// (bh, l, d) head-major layout. grid = (8, 12, 3), block = 256.
// 64x64 output tile, 16-wide K tiles, 4x4 micro-tile per thread.
// ---------------------------------------------------------------------------
__global__ __launch_bounds__(256) void qkv_gemm_kernel(
    const float* __restrict__ x,
    const float* __restrict__ Wq,
    const float* __restrict__ Wk,
    const float* __restrict__ Wv)
{
    __shared__ __align__(16) float As[16][64];
    __shared__ __align__(16) float Bs[16][64];

    const int which = blockIdx.z;
    const float* W = (which == 0) ? Wq : (which == 1 ? Wk : Wv);
    float* out = (which == 0) ? g_q : (which == 1 ? g_k : g_v);

    const int m0 = blockIdx.y * 64;
    const int n0 = blockIdx.x * 64;
    const int tid = threadIdx.x;
    const int tx = tid & 15;
    const int ty = tid >> 4;
    const int lrow = tid >> 2;          // 0..63
    const int lk4 = (tid & 3) << 2;     // 0,4,8,12

    const float* Ap = x + (m0 + lrow) * EE;
    const float* Bp = W + (n0 + lrow) * EE;

    float acc[4][4];
#pragma unroll
    for (int i = 0; i < 4; i++)
#pragma unroll
        for (int j = 0; j < 4; j++) acc[i][j] = 0.0f;

    for (int k0 = 0; k0 < EE; k0 += 16) {
        float4 av = *(const float4*)(Ap + k0 + lk4);
        float4 bv = *(const float4*)(Bp + k0 + lk4);
        As[lk4 + 0][lrow] = av.x; As[lk4 + 1][lrow] = av.y;
        As[lk4 + 2][lrow] = av.z; As[lk4 + 3][lrow] = av.w;
        Bs[lk4 + 0][lrow] = bv.x; Bs[lk4 + 1][lrow] = bv.y;
        Bs[lk4 + 2][lrow] = bv.z; Bs[lk4 + 3][lrow] = bv.w;
        __syncthreads();
#pragma unroll
        for (int kk = 0; kk < 16; kk++) {
            float4 a4 = *(const float4*)&As[kk][ty << 2];
            float4 b4 = *(const float4*)&Bs[kk][tx << 2];
            acc[0][0] += a4.x * b4.x; acc[0][1] += a4.x * b4.y;
            acc[0][2] += a4.x * b4.z; acc[0][3] += a4.x * b4.w;
            acc[1][0] += a4.y * b4.x; acc[1][1] += a4.y * b4.y;
            acc[1][2] += a4.y * b4.z; acc[1][3] += a4.y * b4.w;
            acc[2][0] += a4.z * b4.x; acc[2][1] += a4.z * b4.y;
            acc[2][2] += a4.z * b4.z; acc[2][3] += a4.z * b4.w;
            acc[3][0] += a4.w * b4.x; acc[3][1] += a4.w * b4.y;
            acc[3][2] += a4.w * b4.z; acc[3][3] += a4.w * b4.w;
        }
        __syncthreads();
    }

    // Scatter to head-major (bh, l, d). Tile is fully inside one b (384 % 64
    // == 0) and one head (n0 multiple of 64).
    const int b = m0 / LL;
    const int h = n0 >> 6;
    const int lbase = m0 - b * LL;
#pragma unroll
    for (int i = 0; i < 4; i++) {
        int l = lbase + (ty << 2) + i;
        float4 vst = make_float4(acc[i][0], acc[i][1], acc[i][2], acc[i][3]);
        *(float4*)(out + (((b << 3) + h) * LL + l) * HD + (tx << 2)) = vst;
    }
}

// ---------------------------------------------------------------------------
// Quaternion attention. grid = (6, 16, 8), block = 128.
// 2 threads per query row (8 atoms each), K/V chunk in smem,
// gate mean via one shfl_xor, fp32 FMA throughout.
// ---------------------------------------------------------------------------
__global__ __launch_bounds__(128) void attn_kernel(
    const float* __restrict__ dde_w,
    const float* __restrict__ dde_b)
{
    __shared__ float4 sk[JCHUNK * CATOMS];
    __shared__ float4 sv[JCHUNK * CATOMS];

    const int tid = threadIdx.x;
    const int rb = blockIdx.x;   // row block (64 rows)
    const int bh = blockIdx.y;
    const int js = blockIdx.z;
    const int j0 = js * JCHUNK;

    // Stage K/V chunk: 48 keys x 16 atoms (float4) each
    const float4* kg = (const float4*)(g_k + (bh * LL + j0) * HD);
    const float4* vg = (const float4*)(g_v + (bh * LL + j0) * HD);
    for (int t = tid; t < JCHUNK * CATOMS; t += 128) {
        sk[t] = kg[t];
        sv[t] = vg[t];
    }

    // Gate weights into registers (broadcast loads)
    float w[16], bvec[4];
#pragma unroll
    for (int p = 0; p < 16; p++) w[p] = __ldg(&dde_w[p]);
#pragma unroll
    for (int p = 0; p < 4; p++) bvec[p] = __ldg(&dde_b[p]);

    const int row = rb * 64 + (tid >> 1);
    const int half = tid & 1;

    // q atoms (this thread owns 8 of 16)
    float4 q[8];
    const float4* qg = (const float4*)(g_q + (bh * LL + row) * HD);
#pragma unroll
    for (int a = 0; a < 8; a++) q[a] = qg[half * 8 + a];

    float4 ctx[8];
#pragma unroll
    for (int a = 0; a < 8; a++) ctx[a] = make_float4(0.f, 0.f, 0.f, 0.f);

    __syncthreads();

    for (int jj = 0; jj < JCHUNK; jj++) {
        float4 s[8];
        float g0 = 0.f, g1 = 0.f, g2 = 0.f, g3 = 0.f;
        const float4* kbase = &sk[jj * CATOMS + half * 8];
#pragma unroll
        for (int a = 0; a < 8; a++) {
            float4 kk = kbase[a];
            float4 qa = q[a];
            // Hamilton(q, k); memory order (.x,.y,.z,.w) = (w,x,y,z)
            float hw = qa.x * kk.x - qa.y * kk.y - qa.z * kk.z - qa.w * kk.w;
            float hx = qa.x * kk.y + qa.y * kk.x + qa.z * kk.w - qa.w * kk.z;
            float hy = qa.x * kk.z - qa.y * kk.w + qa.z * kk.x + qa.w * kk.y;
            float hz = qa.x * kk.w + qa.y * kk.z - qa.z * kk.y + qa.w * kk.x;
            float d = hw * hw + hx * hx + hy * hy + hz * hz;
            float inv = __fdividef(1.0f, sqrtf(d) + EPSQ);
            float4 sa = make_float4(hw * inv, hx * inv, hy * inv, hz * inv);
            s[a] = sa;
            g0 += sa.x; g1 += sa.y; g2 += sa.z; g3 += sa.w;
        }
        // Sum across the row's two halves -> full 16-atom sum on both lanes
        g0 += __shfl_xor_sync(0xffffffffu, g0, 1);
        g1 += __shfl_xor_sync(0xffffffffu, g1, 1);
        g2 += __shfl_xor_sync(0xffffffffu, g2, 1);
        g3 += __shfl_xor_sync(0xffffffffu, g3, 1);
        const float inv16 = 1.0f / 16.0f;
        g0 *= inv16; g1 *= inv16; g2 *= inv16; g3 *= inv16;

        float gate[4];
#pragma unroll
        for (int p = 0; p < 4; p++) {
            float z = w[p * 4 + 0] * g0 + w[p * 4 + 1] * g1 +
                      w[p * 4 + 2] * g2 + w[p * 4 + 3] * g3 + bvec[p];
            gate[p] = __fdividef(1.0f, 1.0f + __expf(-z));
        }

        const float4* vbase = &sv[jj * CATOMS + half * 8];
#pragma unroll
        for (int a = 0; a < 8; a++) {
            float4 vv = vbase[a];
            float aw = s[a].x * gate[0];
            float ax = s[a].y * gate[1];
            float ay = s[a].z * gate[2];
            float az = s[a].w * gate[3];
            ctx[a].x += aw * vv.x - ax * vv.y - ay * vv.z - az * vv.w;
            ctx[a].y += aw * vv.y + ax * vv.x + ay * vv.w - az * vv.z;
            ctx[a].z += aw * vv.z - ax * vv.w + ay * vv.x + az * vv.y;
            ctx[a].w += aw * vv.w + ax * vv.z - ay * vv.y + az * vv.x;
        }
    }

    float4* pg = (float4*)(g_part + ((size_t)(js * BH + bh) * LL + row) * HD);
#pragma unroll
    for (int a = 0; a < 8; a++) pg[half * 8 + a] = ctx[a];
}

// ---------------------------------------------------------------------------
// Reduce JS partials + permute (bh,l,d) -> (m, e) GEMM layout.
// grid = 384, block = 256 (one float4 of g_ctx per thread).
// ---------------------------------------------------------------------------
__global__ __launch_bounds__(256) void reduce_kernel()
{
    int idx = blockIdx.x * 256 + threadIdx.x;     // over 98304 float4s
    int flat = idx << 2;
    int m = flat >> 9;            // /512
    int e = flat & 511;
    int b = m / LL;
    int l = m - b * LL;
    int h = e >> 6;
    int d = e & 63;
    float4 acc = make_float4(0.f, 0.f, 0.f, 0.f);
#pragma unroll
    for (int js = 0; js < JS; js++) {
        float4 p = *(const float4*)(g_part +
            ((size_t)(js * BH + (b << 3) + h) * LL + l) * HD + d);
        acc.x += p.x; acc.y += p.y; acc.z += p.z; acc.w += p.w;
    }
    *(float4*)(g_ctx + flat) = acc;
}

// ---------------------------------------------------------------------------
// Output projection: out[m,f] = sum_e ctx[m,e] * Wo[f,e].
// grid = (8, 12), block = 256. Same tiling as qkv_gemm.
// ---------------------------------------------------------------------------
__global__ __launch_bounds__(256) void out_gemm_kernel(
    const float* __restrict__ Wo, float* __restrict__ out)
{
    __shared__ __align__(16) float As[16][64];
    __shared__ __align__(16) float Bs[16][64];

    const int m0 = blockIdx.y * 64;
    const int n0 = blockIdx.x * 64;
    const int tid = threadIdx.x;
    const int tx = tid & 15;
    const int ty = tid >> 4;
    const int lrow = tid >> 2;
    const int lk4 = (tid & 3) << 2;

    const float* Ap = g_ctx + (m0 + lrow) * EE;
    const float* Bp = Wo + (n0 + lrow) * EE;

    float acc[4][4];
#pragma unroll
    for (int i = 0; i < 4; i++)
#pragma unroll
        for (int j = 0; j < 4; j++) acc[i][j] = 0.0f;

    for (int k0 = 0; k0 < EE; k0 += 16) {
        float4 av = *(const float4*)(Ap + k0 + lk4);
        float4 bv = *(const float4*)(Bp + k0 + lk4);
        As[lk4 + 0][lrow] = av.x; As[lk4 + 1][lrow] = av.y;
        As[lk4 + 2][lrow] = av.z; As[lk4 + 3][lrow] = av.w;
        Bs[lk4 + 0][lrow] = bv.x; Bs[lk4 + 1][lrow] = bv.y;
        Bs[lk4 + 2][lrow] = bv.z; Bs[lk4 + 3][lrow] = bv.w;
        __syncthreads();
#pragma unroll
        for (int kk = 0; kk < 16; kk++) {
            float4 a4 = *(const float4*)&As[kk][ty << 2];
            float4 b4 = *(const float4*)&Bs[kk][tx << 2];
            acc[0][0] += a4.x * b4.x; acc[0][1] += a4.x * b4.y;
            acc[0][2] += a4.x * b4.z; acc[0][3] += a4.x * b4.w;
            acc[1][0] += a4.y * b4.x; acc[1][1] += a4.y * b4.y;
            acc[1][2] += a4.y * b4.z; acc[1][3] += a4.y * b4.w;
            acc[2][0] += a4.z * b4.x; acc[2][1] += a4.z * b4.y;
            acc[2][2] += a4.z * b4.z; acc[2][3] += a4.z * b4.w;
            acc[3][0] += a4.w * b4.x; acc[3][1] += a4.w * b4.y;
            acc[3][2] += a4.w * b4.z; acc[3][3] += a4.w * b4.w;
        }
        __syncthreads();
    }

#pragma unroll
    for (int i = 0; i < 4; i++) {
        int m = m0 + (ty << 2) + i;
        float4 vst = make_float4(acc[i][0], acc[i][1], acc[i][2], acc[i][3]);
        *(float4*)(out + m * EE + n0 + (tx << 2)) = vst;
    }
}

// ---------------------------------------------------------------------------
extern "C" void kernel_launch(void* const* d_in, const int* in_sizes, int n_in,
                              void* d_out, int out_size)
{
    const float* x     = (const float*)d_in[0];
    const float* Wq    = (const float*)d_in[1];
    const float* Wk    = (const float*)d_in[2];
    const float* Wv    = (const float*)d_in[3];
    const float* Wo    = (const float*)d_in[4];
    const float* dde_w = (const float*)d_in[5];
    const float* dde_b = (const float*)d_in[6];
    float* out = (float*)d_out;

    qkv_gemm_kernel<<<dim3(8, 12, 3), 256>>>(x, Wq, Wk, Wv);
    attn_kernel<<<dim3(6, BH, JS), 128>>>(dde_w, dde_b);
    reduce_kernel<<<384, 256>>>();
    out_gemm_kernel<<<dim3(8, 12), 256>>>(Wo, out);
}